// round 6
// baseline (speedup 1.0000x reference)
#include <cuda_runtime.h>
#include <cuda_bf16.h>

// DNM_Linear: out[b,o] = relu(0.25 * sum_{m,i} relu(x[b,i]*W[o,m,i] - q[o,m,i]) - 0.05)
// x: [512,512] f32; W,q: [128,8,512] -> flat [1024,512] f32; out: [512,128] f32
//
// 512 thr/CTA (4 warps/SMSP), tile 64x64, thread tile 4 rows x 4 cols.
// Warp = 16 tx x 2 ty; ty splits K parity (zero w/q duplication). f32x2 along K.

#define IN_DIM   512
#define OUT_DIM  128
#define NEUR     1024
#define B_TOT    512
#define KC       32            // k per chunk
#define KKC      16            // k-pairs per chunk
#define NMAC     8             // macro steps per chunk (2 kk each)
#define ROWF     132           // floats per kk-row (64 entities x 2, +4 pad: kills store conflicts)
#define ARR      (KKC*ROWF)    // 2112 floats
#define BUF      (3*ARR)
#define SMEM_BYTES (2*BUF*4)   // 50688 B

typedef unsigned long long u64;

__device__ __forceinline__ u64 fma2(u64 a, u64 b, u64 c) {
    u64 d; asm("fma.rn.f32x2 %0, %1, %2, %3;" : "=l"(d) : "l"(a), "l"(b), "l"(c)); return d;
}
__device__ __forceinline__ u64 add2(u64 a, u64 b) {
    u64 d; asm("add.rn.f32x2 %0, %1, %2;" : "=l"(d) : "l"(a), "l"(b)); return d;
}
__device__ __forceinline__ u64 relu2(u64 v) {
    float2 f = *reinterpret_cast<float2*>(&v);
    f.x = fmaxf(f.x, 0.f);
    f.y = fmaxf(f.y, 0.f);
    return *reinterpret_cast<u64*>(&f);
}

extern __shared__ float smem[];

__global__ __launch_bounds__(512, 1)
void dnm_kernel(const float* __restrict__ x,
                const float* __restrict__ W,
                const float* __restrict__ q,
                float* __restrict__ out)
{
    const int t    = threadIdx.x;
    const int lane = t & 31;
    const int wid  = t >> 5;          // 0..15 -> rows wid*4 .. wid*4+3
    const int tx   = lane & 15;
    const int ty   = lane >> 4;       // kk parity within macro step
    const int n0   = blockIdx.x * 64;
    const int b0   = blockIdx.y * 64;

    // global load mapping: 8 threads per entity row, 1 float4 (4 k) each
    const int e  = t >> 3;            // 0..63
    const int kq = (t & 7) * 4;       // 0,4,...,28
    const float* xg = x + (size_t)(b0 + e) * IN_DIM + kq;
    const float* wg = W + (size_t)(n0 + e) * IN_DIM + kq;
    const float* qg = q + (size_t)(n0 + e) * IN_DIM + kq;
    const int kk0 = kq >> 1;          // (t&7)*2

    // acc[r][j]: rows wid*4+r; j=0,1 -> cols {2tx,2tx+1}; j=2,3 -> {32+2tx,33+2tx}
    u64 acc[4][4];
#pragma unroll
    for (int r = 0; r < 4; r++)
#pragma unroll
        for (int j = 0; j < 4; j++) acc[r][j] = 0ull;

    float4 px, pw, pq;

    // ---- prologue: load + store chunk 0
    px = *(const float4*)xg;
    pw = *(const float4*)wg;
    pq = *(const float4*)qg;
    {
        float* bx = smem;
        float* bw = smem + ARR;
        float* bq = smem + 2 * ARR;
        *(float2*)(bx + (kk0    ) * ROWF + e * 2) = make_float2(px.x,  px.y);
        *(float2*)(bx + (kk0 + 1) * ROWF + e * 2) = make_float2(px.z,  px.w);
        *(float2*)(bw + (kk0    ) * ROWF + e * 2) = make_float2(pw.x,  pw.y);
        *(float2*)(bw + (kk0 + 1) * ROWF + e * 2) = make_float2(pw.z,  pw.w);
        *(float2*)(bq + (kk0    ) * ROWF + e * 2) = make_float2(-pq.x, -pq.y);
        *(float2*)(bq + (kk0 + 1) * ROWF + e * 2) = make_float2(-pq.z, -pq.w);
    }
    __syncthreads();

    const int NCHUNK = IN_DIM / KC;   // 16
    for (int c = 0; c < NCHUNK; c++) {
        // prefetch next chunk (overlaps compute)
        if (c < NCHUNK - 1) {
            const int kn = (c + 1) * KC;
            px = *(const float4*)(xg + kn);
            pw = *(const float4*)(wg + kn);
            pq = *(const float4*)(qg + kn);
        }

        const float* cb = smem + (c & 1) * BUF;
        const float* bx = cb + ty * ROWF + wid * 8;           // 4 rows (2 float4)
        const float* bw = cb + ARR + ty * ROWF + tx * 4;      // granules tx, 16+tx
        const float* bq = cb + 2 * ARR + ty * ROWF + tx * 4;

#pragma unroll
        for (int m = 0; m < NMAC; m++) {
            const int off = m * (2 * ROWF);
            float4 xv0 = *(const float4*)(bx + off);          // rows 0-1 (k-pairs)
            float4 xv1 = *(const float4*)(bx + off + 4);      // rows 2-3
            float4 wv0 = *(const float4*)(bw + off);          // cols 2tx, 2tx+1
            float4 wv1 = *(const float4*)(bw + off + 64);     // cols 32+2tx, 33+2tx
            float4 qv0 = *(const float4*)(bq + off);
            float4 qv1 = *(const float4*)(bq + off + 64);

            u64 ux[4] = { *(u64*)&xv0.x, *(u64*)&xv0.z,
                          *(u64*)&xv1.x, *(u64*)&xv1.z };
            u64 uw[4] = { *(u64*)&wv0.x, *(u64*)&wv0.z,
                          *(u64*)&wv1.x, *(u64*)&wv1.z };
            u64 uq[4] = { *(u64*)&qv0.x, *(u64*)&qv0.z,
                          *(u64*)&qv1.x, *(u64*)&qv1.z };

#pragma unroll
            for (int r = 0; r < 4; r++)
#pragma unroll
                for (int j = 0; j < 4; j++)
                    acc[r][j] = add2(acc[r][j], relu2(fma2(ux[r], uw[j], uq[j])));
        }

        // store prefetched chunk into the other buffer
        if (c < NCHUNK - 1) {
            float* nb = smem + ((c + 1) & 1) * BUF;
            float* bx2 = nb;
            float* bw2 = nb + ARR;
            float* bq2 = nb + 2 * ARR;
            *(float2*)(bx2 + (kk0    ) * ROWF + e * 2) = make_float2(px.x,  px.y);
            *(float2*)(bx2 + (kk0 + 1) * ROWF + e * 2) = make_float2(px.z,  px.w);
            *(float2*)(bw2 + (kk0    ) * ROWF + e * 2) = make_float2(pw.x,  pw.y);
            *(float2*)(bw2 + (kk0 + 1) * ROWF + e * 2) = make_float2(pw.z,  pw.w);
            *(float2*)(bq2 + (kk0    ) * ROWF + e * 2) = make_float2(-pq.x, -pq.y);
            *(float2*)(bq2 + (kk0 + 1) * ROWF + e * 2) = make_float2(-pq.z, -pq.w);
        }
        __syncthreads();
    }

    // ---- epilogue: fold k-parity (xor16), then 8-neuron groups (xor1, xor2)
    const unsigned FULL = 0xffffffffu;
#pragma unroll
    for (int r = 0; r < 4; r++) {
        float2 a0 = *reinterpret_cast<float2*>(&acc[r][0]);
        float2 a1 = *reinterpret_cast<float2*>(&acc[r][1]);
        float2 a2 = *reinterpret_cast<float2*>(&acc[r][2]);
        float2 a3 = *reinterpret_cast<float2*>(&acc[r][3]);
        float sA = a0.x + a0.y + a1.x + a1.y;   // cols 2tx, 2tx+1
        float sB = a2.x + a2.y + a3.x + a3.y;   // cols 32+2tx, 33+2tx

        sA += __shfl_xor_sync(FULL, sA, 16);    // fold k parity
        sB += __shfl_xor_sync(FULL, sB, 16);
        sA += __shfl_xor_sync(FULL, sA, 1);     // fold lanes -> 8-neuron groups
        sB += __shfl_xor_sync(FULL, sB, 1);
        sA += __shfl_xor_sync(FULL, sA, 2);
        sB += __shfl_xor_sync(FULL, sB, 2);

        if ((lane & 19) == 0) {                 // ty==0 && (tx&3)==0
            const int b  = b0 + wid * 4 + r;
            const int g  = tx >> 2;             // 0..3
            const int ob = n0 >> 3;
            out[b * OUT_DIM + ob + g]     = fmaxf(0.25f * sA - 0.05f, 0.f);
            out[b * OUT_DIM + ob + 4 + g] = fmaxf(0.25f * sB - 0.05f, 0.f);
        }
    }
}

extern "C" void kernel_launch(void* const* d_in, const int* in_sizes, int n_in,
                              void* d_out, int out_size)
{
    const float* x = (const float*)d_in[0];
    const float* W = (const float*)d_in[1];
    const float* q = (const float*)d_in[2];
    float* out = (float*)d_out;

    cudaFuncSetAttribute(dnm_kernel, cudaFuncAttributeMaxDynamicSharedMemorySize, SMEM_BYTES);

    dim3 grid(NEUR / 64, B_TOT / 64);   // 16 x 8 = 128 CTAs, 512 threads each
    dnm_kernel<<<grid, 512, SMEM_BYTES>>>(x, W, q, out);
}

// round 8
// speedup vs baseline: 1.0662x; 1.0662x over previous
#include <cuda_runtime.h>
#include <cuda_bf16.h>

// DNM_Linear: out[b,o] = relu(0.25 * sum_{m,i} relu(x[b,i]*W[o,m,i] - q[o,m,i]) - 0.05)
// x: [512,512] f32; W,q: [128,8,512] -> flat [1024,512] f32; out: [512,128] f32
//
// 512 thr/CTA (4 warps/SMSP), tile 64x64, thread tile 4x4, ty splits K parity,
// f32x2 packed along K. Register-pipelined smem operands (macro m+1 loads
// overlap macro m math); smem stores hoisted mid-loop.

#define IN_DIM   512
#define OUT_DIM  128
#define NEUR     1024
#define B_TOT    512
#define KC       32
#define KKC      16
#define NMAC     8             // macro steps per chunk (2 kk each)
#define ROWF     132           // 64 entity-pairs + 4 pad floats
#define ARR      (KKC*ROWF)
#define BUF      (3*ARR)
#define SMEM_BYTES (2*BUF*4)   // 50688 B

typedef unsigned long long u64;

__device__ __forceinline__ u64 fma2(u64 a, u64 b, u64 c) {
    u64 d; asm("fma.rn.f32x2 %0, %1, %2, %3;" : "=l"(d) : "l"(a), "l"(b), "l"(c)); return d;
}
__device__ __forceinline__ u64 add2(u64 a, u64 b) {
    u64 d; asm("add.rn.f32x2 %0, %1, %2;" : "=l"(d) : "l"(a), "l"(b)); return d;
}
__device__ __forceinline__ u64 relu2(u64 v) {
    float2 f = *reinterpret_cast<float2*>(&v);
    f.x = fmaxf(f.x, 0.f);
    f.y = fmaxf(f.y, 0.f);
    return *reinterpret_cast<u64*>(&f);
}

extern __shared__ float smem[];

__global__ __launch_bounds__(512, 1)
void dnm_kernel(const float* __restrict__ x,
                const float* __restrict__ W,
                const float* __restrict__ q,
                float* __restrict__ out)
{
    const int t    = threadIdx.x;
    const int lane = t & 31;
    const int wid  = t >> 5;          // rows wid*4 .. wid*4+3
    const int tx   = lane & 15;
    const int ty   = lane >> 4;       // kk parity within macro step
    const int n0   = blockIdx.x * 64;
    const int b0   = blockIdx.y * 64;

    // global load mapping: 8 threads per entity row, 1 float4 each
    const int e  = t >> 3;
    const int kq = (t & 7) * 4;
    const float* xg = x + (size_t)(b0 + e) * IN_DIM + kq;
    const float* wg = W + (size_t)(n0 + e) * IN_DIM + kq;
    const float* qg = q + (size_t)(n0 + e) * IN_DIM + kq;
    const int kk0 = kq >> 1;

    u64 acc[4][4];
#pragma unroll
    for (int r = 0; r < 4; r++)
#pragma unroll
        for (int j = 0; j < 4; j++) acc[r][j] = 0ull;

    float4 px, pw, pq;

    // ---- prologue: load + store chunk 0
    px = *(const float4*)xg;
    pw = *(const float4*)wg;
    pq = *(const float4*)qg;
    {
        float* bx = smem;
        float* bw = smem + ARR;
        float* bq = smem + 2 * ARR;
        *(float2*)(bx + (kk0    ) * ROWF + e * 2) = make_float2(px.x,  px.y);
        *(float2*)(bx + (kk0 + 1) * ROWF + e * 2) = make_float2(px.z,  px.w);
        *(float2*)(bw + (kk0    ) * ROWF + e * 2) = make_float2(pw.x,  pw.y);
        *(float2*)(bw + (kk0 + 1) * ROWF + e * 2) = make_float2(pw.z,  pw.w);
        *(float2*)(bq + (kk0    ) * ROWF + e * 2) = make_float2(-pq.x, -pq.y);
        *(float2*)(bq + (kk0 + 1) * ROWF + e * 2) = make_float2(-pq.z, -pq.w);
    }
    __syncthreads();

    const int NCHUNK = IN_DIM / KC;   // 16

    for (int c = 0; c < NCHUNK; c++) {
        // global prefetch for chunk c+1 (stored mid-loop below)
        if (c < NCHUNK - 1) {
            const int kn = (c + 1) * KC;
            px = *(const float4*)(xg + kn);
            pw = *(const float4*)(wg + kn);
            pq = *(const float4*)(qg + kn);
        }

        const float* cb = smem + (c & 1) * BUF;
        const float* bx = cb + ty * ROWF + wid * 8;
        const float* bw = cb + ARR + ty * ROWF + tx * 4;
        const float* bq = cb + 2 * ARR + ty * ROWF + tx * 4;

        // register-pipelined operands: [2] buffers x {x0,x1,w0,w1,q0,q1}
        float4 Xv[2][2], Wv[2][2], Qv[2][2];

        // load macro 0
        Xv[0][0] = *(const float4*)(bx);
        Xv[0][1] = *(const float4*)(bx + 4);
        Wv[0][0] = *(const float4*)(bw);
        Wv[0][1] = *(const float4*)(bw + 64);
        Qv[0][0] = *(const float4*)(bq);
        Qv[0][1] = *(const float4*)(bq + 64);

#pragma unroll
        for (int m = 0; m < NMAC; m++) {
            const int cur = m & 1;
            const int nxt = cur ^ 1;

            // prefetch macro m+1 operands (overlaps math below)
            if (m < NMAC - 1) {
                const int off = (m + 1) * (2 * ROWF);
                Xv[nxt][0] = *(const float4*)(bx + off);
                Xv[nxt][1] = *(const float4*)(bx + off + 4);
                Wv[nxt][0] = *(const float4*)(bw + off);
                Wv[nxt][1] = *(const float4*)(bw + off + 64);
                Qv[nxt][0] = *(const float4*)(bq + off);
                Qv[nxt][1] = *(const float4*)(bq + off + 64);
            }

            // mid-loop: store prefetched globals into the other smem buffer
            // (legal: that buffer's readers finished before last chunk's sync)
            if (m == 4 && c < NCHUNK - 1) {
                float* nb = smem + ((c + 1) & 1) * BUF;
                float* bx2 = nb;
                float* bw2 = nb + ARR;
                float* bq2 = nb + 2 * ARR;
                *(float2*)(bx2 + (kk0    ) * ROWF + e * 2) = make_float2(px.x,  px.y);
                *(float2*)(bx2 + (kk0 + 1) * ROWF + e * 2) = make_float2(px.z,  px.w);
                *(float2*)(bw2 + (kk0    ) * ROWF + e * 2) = make_float2(pw.x,  pw.y);
                *(float2*)(bw2 + (kk0 + 1) * ROWF + e * 2) = make_float2(pw.z,  pw.w);
                *(float2*)(bq2 + (kk0    ) * ROWF + e * 2) = make_float2(-pq.x, -pq.y);
                *(float2*)(bq2 + (kk0 + 1) * ROWF + e * 2) = make_float2(-pq.z, -pq.w);
            }

            u64 ux[4] = { *(u64*)&Xv[cur][0].x, *(u64*)&Xv[cur][0].z,
                          *(u64*)&Xv[cur][1].x, *(u64*)&Xv[cur][1].z };
            u64 uw[4] = { *(u64*)&Wv[cur][0].x, *(u64*)&Wv[cur][0].z,
                          *(u64*)&Wv[cur][1].x, *(u64*)&Wv[cur][1].z };
            u64 uq[4] = { *(u64*)&Qv[cur][0].x, *(u64*)&Qv[cur][0].z,
                          *(u64*)&Qv[cur][1].x, *(u64*)&Qv[cur][1].z };

#pragma unroll
            for (int r = 0; r < 4; r++)
#pragma unroll
                for (int j = 0; j < 4; j++)
                    acc[r][j] = add2(acc[r][j], relu2(fma2(ux[r], uw[j], uq[j])));
        }

        __syncthreads();
    }

    // ---- epilogue: fold k-parity (xor16), then 8-neuron groups (xor1, xor2)
    const unsigned FULL = 0xffffffffu;
#pragma unroll
    for (int r = 0; r < 4; r++) {
        float2 a0 = *reinterpret_cast<float2*>(&acc[r][0]);
        float2 a1 = *reinterpret_cast<float2*>(&acc[r][1]);
        float2 a2 = *reinterpret_cast<float2*>(&acc[r][2]);
        float2 a3 = *reinterpret_cast<float2*>(&acc[r][3]);
        float sA = a0.x + a0.y + a1.x + a1.y;   // cols 2tx, 2tx+1
        float sB = a2.x + a2.y + a3.x + a3.y;   // cols 32+2tx, 33+2tx

        sA += __shfl_xor_sync(FULL, sA, 16);
        sB += __shfl_xor_sync(FULL, sB, 16);
        sA += __shfl_xor_sync(FULL, sA, 1);
        sB += __shfl_xor_sync(FULL, sB, 1);
        sA += __shfl_xor_sync(FULL, sA, 2);
        sB += __shfl_xor_sync(FULL, sB, 2);

        if ((lane & 19) == 0) {                 // ty==0 && (tx&3)==0
            const int b  = b0 + wid * 4 + r;
            const int g  = tx >> 2;
            const int ob = n0 >> 3;
            out[b * OUT_DIM + ob + g]     = fmaxf(0.25f * sA - 0.05f, 0.f);
            out[b * OUT_DIM + ob + 4 + g] = fmaxf(0.25f * sB - 0.05f, 0.f);
        }
    }
}

extern "C" void kernel_launch(void* const* d_in, const int* in_sizes, int n_in,
                              void* d_out, int out_size)
{
    const float* x = (const float*)d_in[0];
    const float* W = (const float*)d_in[1];
    const float* q = (const float*)d_in[2];
    float* out = (float*)d_out;

    cudaFuncSetAttribute(dnm_kernel, cudaFuncAttributeMaxDynamicSharedMemorySize, SMEM_BYTES);

    dim3 grid(NEUR / 64, B_TOT / 64);   // 128 CTAs, 512 threads
    dnm_kernel<<<grid, 512, SMEM_BYTES>>>(x, W, q, out);
}